// round 9
// baseline (speedup 1.0000x reference)
#include <cuda_runtime.h>
#include <cuda_fp16.h>
#include <cstdint>
#include <cstddef>

#define Bv   32
#define Tv   256
#define Iv   512
#define Cv   512
#define G4   2048
#define NBv  8

// ---------------- scratch (static device globals; no allocations) ----------------
__device__ float g_c[Bv * NBv];              // mixture coefficients
__device__ int   g_len[Bv];                  // sequence lengths
__device__ float g_bias[2 * Bv * G4];        // mixed biases per dir
__device__ __align__(16) __half g_Whh16[(size_t)2 * Bv * G4 * Cv];   // 134 MB fp16
__device__ __align__(16) float  g_Wih_mix[(size_t)Bv * G4 * Iv];     // 134 MB fp32 (reused per dir)
__device__ __align__(16) float  g_Xproj[(size_t)2 * Bv * Tv * G4];   // 134 MB fp32
__device__ __align__(16) float  g_h[2 * 2 * Bv * Cv];                // ping-pong h per dir
__device__ __align__(16) float  g_cst[2 * Bv * Cv];                  // c state per dir

// ---------------- prep: lengths + mixture coefficients ----------------
// mask dtype detection: batch 0 has length T (all-true row), so the first 4
// bytes are: uint8 -> 0x01010101, int32 -> 0x00000001, float32 -> 0x3f800000.
__global__ __launch_bounds__(128) void prep_kernel(
    const unsigned char* __restrict__ mask8,
    const int* __restrict__ ma, const int* __restrict__ mc,
    const float* __restrict__ ea, const float* __restrict__ ec,
    const float* __restrict__ pw1, const float* __restrict__ pb1,
    const float* __restrict__ pw2)
{
    int b = blockIdx.x, tid = threadIdx.x;
    __shared__ float q[128];
    __shared__ float h1[64];
    __shared__ float lg[8];
    __shared__ int   redi[128];
    __shared__ int   mode;

    if (tid == 0) {
        unsigned w0 = *reinterpret_cast<const unsigned*>(mask8);
        if (w0 == 0x01010101u)      mode = 0;   // uint8
        else if (w0 == 1u)          mode = 1;   // int32
        else                        mode = 2;   // float32 (0x3f800000)
    }
    __syncthreads();

    int cnt = 0;
    if (mode == 0) {
        cnt = (int)mask8[b * Tv + tid] + (int)mask8[b * Tv + 128 + tid];
    } else if (mode == 1) {
        const int* m32 = reinterpret_cast<const int*>(mask8);
        cnt = m32[b * Tv + tid] + m32[b * Tv + 128 + tid];
    } else {
        const float* mf = reinterpret_cast<const float*>(mask8);
        cnt = (mf[b * Tv + tid] != 0.f) + (mf[b * Tv + 128 + tid] != 0.f);
    }
    redi[tid] = cnt;
    __syncthreads();
    for (int s = 64; s > 0; s >>= 1) {
        if (tid < s) redi[tid] += redi[tid + s];
        __syncthreads();
    }
    if (tid == 0) g_len[b] = redi[0];

    int a = ma[b], cidx = mc[b];
    if (tid < 64) q[tid] = ea[a * 64 + tid];
    else          q[tid] = ec[cidx * 64 + (tid - 64)];
    __syncthreads();

    if (tid < 64) {
        float s = pb1[tid];
        #pragma unroll 8
        for (int i = 0; i < 128; i++) s += q[i] * pw1[i * 64 + tid];
        h1[tid] = tanhf(s);
    }
    __syncthreads();
    if (tid < 8) {
        float s = 0.f;
        #pragma unroll 8
        for (int i = 0; i < 64; i++) s += h1[i] * pw2[i * 8 + tid];
        lg[tid] = s;
    }
    __syncthreads();
    if (tid == 0) {
        float m = lg[0];
        #pragma unroll
        for (int n = 1; n < 8; n++) m = fmaxf(m, lg[n]);
        float e[8], sum = 0.f;
        #pragma unroll
        for (int n = 0; n < 8; n++) { e[n] = expf(lg[n] - m); sum += e[n]; }
        float inv = 1.f / sum;
        #pragma unroll
        for (int n = 0; n < 8; n++) g_c[b * 8 + n] = e[n] * inv;
    }
}

// ---------------- mixed biases ----------------
__global__ __launch_bounds__(256) void bias_kernel(
    const float* __restrict__ bf, const float* __restrict__ br)
{
    int idx = blockIdx.x * 256 + threadIdx.x;      // 2*32*2048 = 131072
    int g = idx & 2047;
    int b = (idx >> 11) & 31;
    int d = idx >> 16;
    const float* src = d ? br : bf;                // [8][2048]
    float s = 0.f;
    #pragma unroll
    for (int n = 0; n < 8; n++) s += g_c[b * 8 + n] * src[n * G4 + g];
    g_bias[idx] = s;
}

// ---------------- mix W_hh -> fp16, both dirs ----------------
__global__ __launch_bounds__(256) void mix_hh_kernel(
    const float* __restrict__ Wf, const float* __restrict__ Wr)
{
    __shared__ float cs[Bv * NBv];
    if (threadIdx.x < Bv * NBv) cs[threadIdx.x] = g_c[threadIdx.x];
    __syncthreads();

    int item = blockIdx.x * 256 + threadIdx.x;   // 2*4*2048*64 = 1048576
    int c8 = item & 63;
    int g  = (item >> 6) & 2047;
    int bg = (item >> 17) & 3;
    int d  = item >> 19;
    const float* Wsrc = d ? Wr : Wf;             // [8][2048][512]

    float acc[8][8];
    #pragma unroll
    for (int i = 0; i < 8; i++)
        #pragma unroll
        for (int j = 0; j < 8; j++) acc[i][j] = 0.f;

    const float* wp0 = Wsrc + (size_t)g * 512 + c8 * 8;
    #pragma unroll
    for (int n = 0; n < 8; n++) {
        const float* wp = wp0 + (size_t)n * (G4 * 512);
        float4 wa = *reinterpret_cast<const float4*>(wp);
        float4 wb = *reinterpret_cast<const float4*>(wp + 4);
        #pragma unroll
        for (int bb = 0; bb < 8; bb++) {
            float cc = cs[(bg * 8 + bb) * 8 + n];
            acc[bb][0] += cc * wa.x; acc[bb][1] += cc * wa.y;
            acc[bb][2] += cc * wa.z; acc[bb][3] += cc * wa.w;
            acc[bb][4] += cc * wb.x; acc[bb][5] += cc * wb.y;
            acc[bb][6] += cc * wb.z; acc[bb][7] += cc * wb.w;
        }
    }
    #pragma unroll
    for (int bb = 0; bb < 8; bb++) {
        int b = bg * 8 + bb;
        __half2 o0 = __floats2half2_rn(acc[bb][0], acc[bb][1]);
        __half2 o1 = __floats2half2_rn(acc[bb][2], acc[bb][3]);
        __half2 o2 = __floats2half2_rn(acc[bb][4], acc[bb][5]);
        __half2 o3 = __floats2half2_rn(acc[bb][6], acc[bb][7]);
        uint4 pk;
        pk.x = *reinterpret_cast<unsigned*>(&o0);
        pk.y = *reinterpret_cast<unsigned*>(&o1);
        pk.z = *reinterpret_cast<unsigned*>(&o2);
        pk.w = *reinterpret_cast<unsigned*>(&o3);
        __half* dst = g_Whh16 + ((size_t)((d * Bv + b) * G4 + g)) * 512 + c8 * 8;
        *reinterpret_cast<uint4*>(dst) = pk;
    }
}

// ---------------- mix W_ih -> fp32 (one direction at a time) ----------------
__global__ __launch_bounds__(256) void mix_ih_kernel(const float* __restrict__ Wsrc)
{
    __shared__ float cs[Bv * NBv];
    if (threadIdx.x < Bv * NBv) cs[threadIdx.x] = g_c[threadIdx.x];
    __syncthreads();

    int item = blockIdx.x * 256 + threadIdx.x;   // 4*2048*64 = 524288
    int i8 = item & 63;
    int g  = (item >> 6) & 2047;
    int bg = item >> 17;                          // 0..3

    float acc[8][8];
    #pragma unroll
    for (int i = 0; i < 8; i++)
        #pragma unroll
        for (int j = 0; j < 8; j++) acc[i][j] = 0.f;

    const float* wp0 = Wsrc + (size_t)g * 512 + i8 * 8;
    #pragma unroll
    for (int n = 0; n < 8; n++) {
        const float* wp = wp0 + (size_t)n * (G4 * 512);
        float4 wa = *reinterpret_cast<const float4*>(wp);
        float4 wb = *reinterpret_cast<const float4*>(wp + 4);
        #pragma unroll
        for (int bb = 0; bb < 8; bb++) {
            float cc = cs[(bg * 8 + bb) * 8 + n];
            acc[bb][0] += cc * wa.x; acc[bb][1] += cc * wa.y;
            acc[bb][2] += cc * wa.z; acc[bb][3] += cc * wa.w;
            acc[bb][4] += cc * wb.x; acc[bb][5] += cc * wb.y;
            acc[bb][6] += cc * wb.z; acc[bb][7] += cc * wb.w;
        }
    }
    #pragma unroll
    for (int bb = 0; bb < 8; bb++) {
        int b = bg * 8 + bb;
        float* dst = g_Wih_mix + ((size_t)(b * G4 + g)) * 512 + i8 * 8;
        *reinterpret_cast<float4*>(dst)     = make_float4(acc[bb][0], acc[bb][1], acc[bb][2], acc[bb][3]);
        *reinterpret_cast<float4*>(dst + 4) = make_float4(acc[bb][4], acc[bb][5], acc[bb][6], acc[bb][7]);
    }
}

// ---------------- input projection: Xproj[b,t,:] = Wmix[b] @ x[b,t] + bias ----------------
// 128x128x8 tiled SGEMM per batch. grid (16 ntiles, 2 mtiles, 32 batches), 256 threads.
__global__ __launch_bounds__(256, 2) void proj_kernel(const float* __restrict__ X, int d)
{
    int b  = blockIdx.z;
    int by = blockIdx.y;
    int bx = blockIdx.x;
    const float* A  = X + (size_t)b * Tv * Iv;                 // [256][512]
    const float* Bw = g_Wih_mix + (size_t)b * G4 * Iv;         // [2048][512]
    float* C = g_Xproj + (size_t)(d * Bv + b) * Tv * G4;
    const float* bias = g_bias + (d * Bv + b) * G4;

    __shared__ __align__(16) float As[8][128];
    __shared__ __align__(16) float Bs[8][128];

    int tid = threadIdx.x;
    int lr = tid >> 1;
    int lk = (tid & 1) * 4;
    const float* aptr = A  + (size_t)(by * 128 + lr) * Iv + lk;
    const float* bptr = Bw + (size_t)(bx * 128 + lr) * Iv + lk;
    int tx = tid & 15, ty = tid >> 4;

    float acc[8][8];
    #pragma unroll
    for (int i = 0; i < 8; i++)
        #pragma unroll
        for (int j = 0; j < 8; j++) acc[i][j] = 0.f;

    float4 av = *reinterpret_cast<const float4*>(aptr);
    float4 bv = *reinterpret_cast<const float4*>(bptr);

    for (int k0 = 0; k0 < Iv; k0 += 8) {
        __syncthreads();
        As[lk + 0][lr] = av.x; As[lk + 1][lr] = av.y; As[lk + 2][lr] = av.z; As[lk + 3][lr] = av.w;
        Bs[lk + 0][lr] = bv.x; Bs[lk + 1][lr] = bv.y; Bs[lk + 2][lr] = bv.z; Bs[lk + 3][lr] = bv.w;
        __syncthreads();
        if (k0 + 8 < Iv) {
            av = *reinterpret_cast<const float4*>(aptr + k0 + 8);
            bv = *reinterpret_cast<const float4*>(bptr + k0 + 8);
        }
        #pragma unroll
        for (int kk = 0; kk < 8; kk++) {
            float4 aA = *reinterpret_cast<const float4*>(&As[kk][ty * 8]);
            float4 aB = *reinterpret_cast<const float4*>(&As[kk][ty * 8 + 4]);
            float4 bA = *reinterpret_cast<const float4*>(&Bs[kk][tx * 8]);
            float4 bB = *reinterpret_cast<const float4*>(&Bs[kk][tx * 8 + 4]);
            float ar[8] = {aA.x, aA.y, aA.z, aA.w, aB.x, aB.y, aB.z, aB.w};
            float br[8] = {bA.x, bA.y, bA.z, bA.w, bB.x, bB.y, bB.z, bB.w};
            #pragma unroll
            for (int i = 0; i < 8; i++)
                #pragma unroll
                for (int j = 0; j < 8; j++)
                    acc[i][j] += ar[i] * br[j];
        }
    }

    #pragma unroll
    for (int i = 0; i < 8; i++) {
        int row = by * 128 + ty * 8 + i;
        #pragma unroll
        for (int j = 0; j < 8; j += 4) {
            int col = bx * 128 + tx * 8 + j;
            float4 v = make_float4(acc[i][j + 0] + bias[col + 0],
                                   acc[i][j + 1] + bias[col + 1],
                                   acc[i][j + 2] + bias[col + 2],
                                   acc[i][j + 3] + bias[col + 3]);
            *reinterpret_cast<float4*>(&C[(size_t)row * G4 + col]) = v;
        }
    }
}

// ---------------- zero recurrent state ----------------
__global__ void init_kernel()
{
    int i = blockIdx.x * 256 + threadIdx.x;     // launch 65536 threads
    if (i < 2 * 2 * Bv * Cv) g_h[i] = 0.f;
    if (i < 2 * Bv * Cv)     g_cst[i] = 0.f;
}

// ---------------- one recurrence step, one direction ----------------
__device__ __forceinline__ void fma8(float& acc, uint4 w, float4 h0, float4 h1)
{
    float2 q0 = __half22float2(*reinterpret_cast<const __half2*>(&w.x));
    float2 q1 = __half22float2(*reinterpret_cast<const __half2*>(&w.y));
    float2 q2 = __half22float2(*reinterpret_cast<const __half2*>(&w.z));
    float2 q3 = __half22float2(*reinterpret_cast<const __half2*>(&w.w));
    acc += q0.x * h0.x; acc += q0.y * h0.y; acc += q1.x * h0.z; acc += q1.y * h0.w;
    acc += q2.x * h1.x; acc += q2.y * h1.y; acc += q3.x * h1.z; acc += q3.y * h1.w;
}

__global__ __launch_bounds__(128, 8) void step_kernel(int t, int d, float* __restrict__ out)
{
    const int b = blockIdx.y;
    const int chunk = blockIdx.x;
    const int tid = threadIdx.x;
    __shared__ __align__(16) float hs[Cv];
    __shared__ int s_len;

    const int par = t & 1;
    const float* hin = g_h + ((size_t)((par * 2 + d) * Bv + b)) * Cv;
    #pragma unroll
    for (int i = 0; i < 4; i++) hs[tid + 128 * i] = hin[tid + 128 * i];
    if (tid == 0) s_len = g_len[b];
    __syncthreads();

    const int kh = tid & 1;                 // K-half
    const int cell = chunk * 64 + (tid >> 1);
    const __half* wb = g_Whh16 + ((size_t)((d * Bv + b) * G4 + cell)) * Cv + kh * 256;
    const float* hh = hs + kh * 256;

    float a0 = 0.f, a1 = 0.f, a2 = 0.f, a3 = 0.f;
    #pragma unroll 4
    for (int it = 0; it < 32; it++) {
        float4 h0 = *reinterpret_cast<const float4*>(hh + it * 8);
        float4 h1 = *reinterpret_cast<const float4*>(hh + it * 8 + 4);
        uint4 w0 = *reinterpret_cast<const uint4*>(wb + it * 8);
        uint4 w1 = *reinterpret_cast<const uint4*>(wb + (size_t)1 * 512 * Cv + it * 8);
        uint4 w2 = *reinterpret_cast<const uint4*>(wb + (size_t)2 * 512 * Cv + it * 8);
        uint4 w3 = *reinterpret_cast<const uint4*>(wb + (size_t)3 * 512 * Cv + it * 8);
        fma8(a0, w0, h0, h1);
        fma8(a1, w1, h0, h1);
        fma8(a2, w2, h0, h1);
        fma8(a3, w3, h0, h1);
    }
    // combine K-halves (pair lanes 2j / 2j+1)
    a0 += __shfl_xor_sync(0xffffffffu, a0, 1);
    a1 += __shfl_xor_sync(0xffffffffu, a1, 1);
    a2 += __shfl_xor_sync(0xffffffffu, a2, 1);
    a3 += __shfl_xor_sync(0xffffffffu, a3, 1);

    if (kh == 0) {
        const int t_orig = d ? (Tv - 1 - t) : t;
        const float* xp = g_Xproj + ((size_t)((d * Bv + b) * Tv + t_orig)) * G4 + cell;
        float gi = a0 + xp[0];
        float gf = a1 + xp[512];
        float gg = a2 + xp[1024];
        float go = a3 + xp[1536];
        int sidx = (d * Bv + b) * Cv + cell;
        float cprev = g_cst[sidx];
        float cy, hy;
        if (t_orig < s_len) {
            float si = 1.f / (1.f + expf(-gi));
            float sf = 1.f / (1.f + expf(-gf));
            float so = 1.f / (1.f + expf(-go));
            float tg = tanhf(gg);
            cy = sf * cprev + si * tg;
            hy = so * tanhf(cy);
        } else {
            cy = 0.f; hy = 0.f;
        }
        g_cst[sidx] = cy;
        g_h[((size_t)(((par ^ 1) * 2 + d) * Bv + b)) * Cv + cell] = hy;
        out[((size_t)(b * Tv + t_orig)) * (2 * Cv) + d * Cv + cell] = hy;
    }
}

// ---------------- launch ----------------
extern "C" void kernel_launch(void* const* d_in, const int* in_sizes, int n_in,
                              void* d_out, int out_size)
{
    const float* x    = (const float*)d_in[0];
    const unsigned char* mask8 = (const unsigned char*)d_in[1];
    const int* ma     = (const int*)d_in[2];
    const int* mc     = (const int*)d_in[3];
    const float* ea   = (const float*)d_in[4];
    const float* ec   = (const float*)d_in[5];
    const float* pw1  = (const float*)d_in[6];
    const float* pb1  = (const float*)d_in[7];
    const float* pw2  = (const float*)d_in[8];
    const float* Wih  = (const float*)d_in[9];
    const float* Whh  = (const float*)d_in[10];
    const float* bb   = (const float*)d_in[11];
    const float* Wihr = (const float*)d_in[12];
    const float* Whhr = (const float*)d_in[13];
    const float* bbr  = (const float*)d_in[14];
    float* out = (float*)d_out;

    prep_kernel<<<Bv, 128>>>(mask8, ma, mc, ea, ec, pw1, pb1, pw2);
    bias_kernel<<<(2 * Bv * G4) / 256, 256>>>(bb, bbr);
    mix_hh_kernel<<<(2 * 4 * G4 * 64) / 256, 256>>>(Whh, Whhr);
    init_kernel<<<65536 / 256, 256>>>();

    mix_ih_kernel<<<(4 * G4 * 64) / 256, 256>>>(Wih);
    proj_kernel<<<dim3(16, 2, Bv), 256>>>(x, 0);
    mix_ih_kernel<<<(4 * G4 * 64) / 256, 256>>>(Wihr);
    proj_kernel<<<dim3(16, 2, Bv), 256>>>(x, 1);

    // Phase per direction: 67 MB fp16 weight working set stays L2-resident.
    for (int d = 0; d < 2; d++) {
        for (int t = 0; t < Tv; t++) {
            step_kernel<<<dim3(8, Bv), 128>>>(t, d, out);
        }
    }
}

// round 11
// speedup vs baseline: 2.2991x; 2.2991x over previous
#include <cuda_runtime.h>
#include <cuda_fp16.h>
#include <cstdint>
#include <cstddef>

#define Bv   32
#define Tv   256
#define Iv   512
#define Cv   512
#define G4   2048
#define NBv  8

// ---------------- scratch (static device globals; no allocations) ----------------
__device__ float g_c[Bv * NBv];              // mixture coefficients
__device__ int   g_len[Bv];                  // sequence lengths
__device__ float g_bias[2 * Bv * G4];        // mixed biases per dir
// W_hh mixed, fp16, layout: [(d*32+b)][kb(64)][row(2048)][j(8)]
//   row r = (cell>>6)*256 + gate*64 + (cell&63);  element = W[gate*512+cell][kb*8+j]
__device__ __align__(16) __half g_Whh16[(size_t)2 * Bv * G4 * Cv];   // 134 MB fp16
__device__ __align__(16) float  g_Wih_mix[(size_t)Bv * G4 * Iv];     // 134 MB fp32 (reused per dir)
__device__ __align__(16) float  g_Xproj[(size_t)2 * Bv * Tv * G4];   // 134 MB fp32
__device__ __align__(16) float  g_h[2 * Bv * Cv];                    // h state per (dir,b)
__device__ int g_bar_cnt;                                            // grid barrier counter

// ---------------- prep: lengths + mixture coefficients ----------------
// mask dtype detection: batch 0 has length T (all-true row), so the first 4
// bytes are: uint8 -> 0x01010101, int32 -> 0x00000001, float32 -> 0x3f800000.
__global__ __launch_bounds__(128) void prep_kernel(
    const unsigned char* __restrict__ mask8,
    const int* __restrict__ ma, const int* __restrict__ mc,
    const float* __restrict__ ea, const float* __restrict__ ec,
    const float* __restrict__ pw1, const float* __restrict__ pb1,
    const float* __restrict__ pw2)
{
    int b = blockIdx.x, tid = threadIdx.x;
    __shared__ float q[128];
    __shared__ float h1[64];
    __shared__ float lg[8];
    __shared__ int   redi[128];
    __shared__ int   mode;

    if (tid == 0) {
        unsigned w0 = *reinterpret_cast<const unsigned*>(mask8);
        if (w0 == 0x01010101u)      mode = 0;   // uint8
        else if (w0 == 1u)          mode = 1;   // int32
        else                        mode = 2;   // float32 (0x3f800000)
    }
    __syncthreads();

    int cnt = 0;
    if (mode == 0) {
        cnt = (int)mask8[b * Tv + tid] + (int)mask8[b * Tv + 128 + tid];
    } else if (mode == 1) {
        const int* m32 = reinterpret_cast<const int*>(mask8);
        cnt = m32[b * Tv + tid] + m32[b * Tv + 128 + tid];
    } else {
        const float* mf = reinterpret_cast<const float*>(mask8);
        cnt = (mf[b * Tv + tid] != 0.f) + (mf[b * Tv + 128 + tid] != 0.f);
    }
    redi[tid] = cnt;
    __syncthreads();
    for (int s = 64; s > 0; s >>= 1) {
        if (tid < s) redi[tid] += redi[tid + s];
        __syncthreads();
    }
    if (tid == 0) g_len[b] = redi[0];

    int a = ma[b], cidx = mc[b];
    if (tid < 64) q[tid] = ea[a * 64 + tid];
    else          q[tid] = ec[cidx * 64 + (tid - 64)];
    __syncthreads();

    if (tid < 64) {
        float s = pb1[tid];
        #pragma unroll 8
        for (int i = 0; i < 128; i++) s += q[i] * pw1[i * 64 + tid];
        h1[tid] = tanhf(s);
    }
    __syncthreads();
    if (tid < 8) {
        float s = 0.f;
        #pragma unroll 8
        for (int i = 0; i < 64; i++) s += h1[i] * pw2[i * 8 + tid];
        lg[tid] = s;
    }
    __syncthreads();
    if (tid == 0) {
        float m = lg[0];
        #pragma unroll
        for (int n = 1; n < 8; n++) m = fmaxf(m, lg[n]);
        float e[8], sum = 0.f;
        #pragma unroll
        for (int n = 0; n < 8; n++) { e[n] = expf(lg[n] - m); sum += e[n]; }
        float inv = 1.f / sum;
        #pragma unroll
        for (int n = 0; n < 8; n++) g_c[b * 8 + n] = e[n] * inv;
    }
}

// ---------------- mixed biases ----------------
__global__ __launch_bounds__(256) void bias_kernel(
    const float* __restrict__ bf, const float* __restrict__ br)
{
    int idx = blockIdx.x * 256 + threadIdx.x;      // 2*32*2048 = 131072
    int g = idx & 2047;
    int b = (idx >> 11) & 31;
    int d = idx >> 16;
    const float* src = d ? br : bf;                // [8][2048]
    float s = 0.f;
    #pragma unroll
    for (int n = 0; n < 8; n++) s += g_c[b * 8 + n] * src[n * G4 + g];
    g_bias[idx] = s;
}

// ---------------- mix W_hh -> fp16 (k-blocked transposed + row-permuted), both dirs ----------------
__global__ __launch_bounds__(256) void mix_hh_kernel(
    const float* __restrict__ Wf, const float* __restrict__ Wr)
{
    __shared__ float cs[Bv * NBv];
    if (threadIdx.x < Bv * NBv) cs[threadIdx.x] = g_c[threadIdx.x];
    __syncthreads();

    int item = blockIdx.x * 256 + threadIdx.x;   // 2^20 items
    int g  = item & 2047;                         // fastest -> coalesced writes
    int c8 = (item >> 11) & 63;                   // k-block
    int bg = (item >> 17) & 3;
    int d  = item >> 19;
    const float* Wsrc = d ? Wr : Wf;              // [8][2048][512]

    // permuted row index
    int cell = g & 511;
    int gate = g >> 9;
    int r = ((cell >> 6) << 8) + (gate << 6) + (cell & 63);

    float acc[8][8];
    #pragma unroll
    for (int i = 0; i < 8; i++)
        #pragma unroll
        for (int j = 0; j < 8; j++) acc[i][j] = 0.f;

    const float* wp0 = Wsrc + (size_t)g * 512 + c8 * 8;
    #pragma unroll
    for (int n = 0; n < 8; n++) {
        const float* wp = wp0 + (size_t)n * (G4 * 512);
        float4 wa = *reinterpret_cast<const float4*>(wp);
        float4 wb = *reinterpret_cast<const float4*>(wp + 4);
        #pragma unroll
        for (int bb = 0; bb < 8; bb++) {
            float cc = cs[(bg * 8 + bb) * 8 + n];
            acc[bb][0] += cc * wa.x; acc[bb][1] += cc * wa.y;
            acc[bb][2] += cc * wa.z; acc[bb][3] += cc * wa.w;
            acc[bb][4] += cc * wb.x; acc[bb][5] += cc * wb.y;
            acc[bb][6] += cc * wb.z; acc[bb][7] += cc * wb.w;
        }
    }
    #pragma unroll
    for (int bb = 0; bb < 8; bb++) {
        int b = bg * 8 + bb;
        __half2 o0 = __floats2half2_rn(acc[bb][0], acc[bb][1]);
        __half2 o1 = __floats2half2_rn(acc[bb][2], acc[bb][3]);
        __half2 o2 = __floats2half2_rn(acc[bb][4], acc[bb][5]);
        __half2 o3 = __floats2half2_rn(acc[bb][6], acc[bb][7]);
        uint4 pk;
        pk.x = *reinterpret_cast<unsigned*>(&o0);
        pk.y = *reinterpret_cast<unsigned*>(&o1);
        pk.z = *reinterpret_cast<unsigned*>(&o2);
        pk.w = *reinterpret_cast<unsigned*>(&o3);
        __half* dst = g_Whh16 + (((size_t)(d * Bv + b) * 64 + c8) * G4 + r) * 8;
        *reinterpret_cast<uint4*>(dst) = pk;
    }
}

// ---------------- mix W_ih -> fp32 (one direction at a time) ----------------
__global__ __launch_bounds__(256) void mix_ih_kernel(const float* __restrict__ Wsrc)
{
    __shared__ float cs[Bv * NBv];
    if (threadIdx.x < Bv * NBv) cs[threadIdx.x] = g_c[threadIdx.x];
    __syncthreads();

    int item = blockIdx.x * 256 + threadIdx.x;   // 4*2048*64 = 524288
    int i8 = item & 63;
    int g  = (item >> 6) & 2047;
    int bg = item >> 17;                          // 0..3

    float acc[8][8];
    #pragma unroll
    for (int i = 0; i < 8; i++)
        #pragma unroll
        for (int j = 0; j < 8; j++) acc[i][j] = 0.f;

    const float* wp0 = Wsrc + (size_t)g * 512 + i8 * 8;
    #pragma unroll
    for (int n = 0; n < 8; n++) {
        const float* wp = wp0 + (size_t)n * (G4 * 512);
        float4 wa = *reinterpret_cast<const float4*>(wp);
        float4 wb = *reinterpret_cast<const float4*>(wp + 4);
        #pragma unroll
        for (int bb = 0; bb < 8; bb++) {
            float cc = cs[(bg * 8 + bb) * 8 + n];
            acc[bb][0] += cc * wa.x; acc[bb][1] += cc * wa.y;
            acc[bb][2] += cc * wa.z; acc[bb][3] += cc * wa.w;
            acc[bb][4] += cc * wb.x; acc[bb][5] += cc * wb.y;
            acc[bb][6] += cc * wb.z; acc[bb][7] += cc * wb.w;
        }
    }
    #pragma unroll
    for (int bb = 0; bb < 8; bb++) {
        int b = bg * 8 + bb;
        float* dst = g_Wih_mix + ((size_t)(b * G4 + g)) * 512 + i8 * 8;
        *reinterpret_cast<float4*>(dst)     = make_float4(acc[bb][0], acc[bb][1], acc[bb][2], acc[bb][3]);
        *reinterpret_cast<float4*>(dst + 4) = make_float4(acc[bb][4], acc[bb][5], acc[bb][6], acc[bb][7]);
    }
}

// ---------------- input projection: Xproj[b,t,:] = Wmix[b] @ x[b,t] + bias ----------------
__global__ __launch_bounds__(256, 2) void proj_kernel(const float* __restrict__ X, int d)
{
    int b  = blockIdx.z;
    int by = blockIdx.y;
    int bx = blockIdx.x;
    const float* A  = X + (size_t)b * Tv * Iv;                 // [256][512]
    const float* Bw = g_Wih_mix + (size_t)b * G4 * Iv;         // [2048][512]
    float* C = g_Xproj + (size_t)(d * Bv + b) * Tv * G4;
    const float* bias = g_bias + (d * Bv + b) * G4;

    __shared__ __align__(16) float As[8][128];
    __shared__ __align__(16) float Bs[8][128];

    int tid = threadIdx.x;
    int lr = tid >> 1;
    int lk = (tid & 1) * 4;
    const float* aptr = A  + (size_t)(by * 128 + lr) * Iv + lk;
    const float* bptr = Bw + (size_t)(bx * 128 + lr) * Iv + lk;
    int tx = tid & 15, ty = tid >> 4;

    float acc[8][8];
    #pragma unroll
    for (int i = 0; i < 8; i++)
        #pragma unroll
        for (int j = 0; j < 8; j++) acc[i][j] = 0.f;

    float4 av = *reinterpret_cast<const float4*>(aptr);
    float4 bv = *reinterpret_cast<const float4*>(bptr);

    for (int k0 = 0; k0 < Iv; k0 += 8) {
        __syncthreads();
        As[lk + 0][lr] = av.x; As[lk + 1][lr] = av.y; As[lk + 2][lr] = av.z; As[lk + 3][lr] = av.w;
        Bs[lk + 0][lr] = bv.x; Bs[lk + 1][lr] = bv.y; Bs[lk + 2][lr] = bv.z; Bs[lk + 3][lr] = bv.w;
        __syncthreads();
        if (k0 + 8 < Iv) {
            av = *reinterpret_cast<const float4*>(aptr + k0 + 8);
            bv = *reinterpret_cast<const float4*>(bptr + k0 + 8);
        }
        #pragma unroll
        for (int kk = 0; kk < 8; kk++) {
            float4 aA = *reinterpret_cast<const float4*>(&As[kk][ty * 8]);
            float4 aB = *reinterpret_cast<const float4*>(&As[kk][ty * 8 + 4]);
            float4 bA = *reinterpret_cast<const float4*>(&Bs[kk][tx * 8]);
            float4 bB = *reinterpret_cast<const float4*>(&Bs[kk][tx * 8 + 4]);
            float ar[8] = {aA.x, aA.y, aA.z, aA.w, aB.x, aB.y, aB.z, aB.w};
            float br[8] = {bA.x, bA.y, bA.z, bA.w, bB.x, bB.y, bB.z, bB.w};
            #pragma unroll
            for (int i = 0; i < 8; i++)
                #pragma unroll
                for (int j = 0; j < 8; j++)
                    acc[i][j] += ar[i] * br[j];
        }
    }

    #pragma unroll
    for (int i = 0; i < 8; i++) {
        int row = by * 128 + ty * 8 + i;
        #pragma unroll
        for (int j = 0; j < 8; j += 4) {
            int col = bx * 128 + tx * 8 + j;
            float4 v = make_float4(acc[i][j + 0] + bias[col + 0],
                                   acc[i][j + 1] + bias[col + 1],
                                   acc[i][j + 2] + bias[col + 2],
                                   acc[i][j + 3] + bias[col + 3]);
            *reinterpret_cast<float4*>(&C[(size_t)row * G4 + col]) = v;
        }
    }
}

// ---------------- zero recurrent state + barrier ----------------
__global__ void init_kernel()
{
    int i = blockIdx.x * 256 + threadIdx.x;
    if (i < 2 * Bv * Cv) g_h[i] = 0.f;
    if (i == 0) g_bar_cnt = 0;
}

// ---------------- persistent recurrence, one direction ----------------
__device__ __forceinline__ void fma8(float& acc, uint4 w, float4 h0, float4 h1)
{
    float2 q0 = __half22float2(*reinterpret_cast<const __half2*>(&w.x));
    float2 q1 = __half22float2(*reinterpret_cast<const __half2*>(&w.y));
    float2 q2 = __half22float2(*reinterpret_cast<const __half2*>(&w.z));
    float2 q3 = __half22float2(*reinterpret_cast<const __half2*>(&w.w));
    acc += q0.x * h0.x; acc += q0.y * h0.y; acc += q1.x * h0.z; acc += q1.y * h0.w;
    acc += q2.x * h1.x; acc += q2.y * h1.y; acc += q3.x * h1.z; acc += q3.y * h1.w;
}

// grid = 256 blocks (b=bid>>3, chunk=bid&7), 256 threads (tid = gate*64 + cell_lo).
// Co-residency guaranteed: 256 blocks <= 148 SMs * 2 (launch_bounds min 2/SM),
// so the software grid barrier cannot deadlock.
__global__ __launch_bounds__(256, 2) void step_persist(int d, float* __restrict__ out)
{
    const int bid = blockIdx.x;
    const int b = bid >> 3;
    const int chunk = bid & 7;
    const int tid = threadIdx.x;

    __shared__ __align__(16) float hs[Cv];
    __shared__ float sg[256];
    __shared__ float sc[64];
    __shared__ int s_len;

    if (tid == 0) s_len = g_len[b];
    if (tid < 64) sc[tid] = 0.f;

    const __half* wbase = g_Whh16 + (size_t)(d * Bv + b) * (64ull * G4 * 8)
                        + (size_t)(chunk * 256 + tid) * 8;
    const float* hin = g_h + (d * Bv + b) * Cv;
    float* hout = g_h + (d * Bv + b) * Cv;
    const int cell = chunk * 64 + (tid & 63);
    const float* xbase = g_Xproj + (size_t)(d * Bv + b) * Tv * G4;

    for (int t = 0; t < Tv; t++) {
        // load h (L2-coherent; written by peer blocks before the grid barrier)
        hs[tid]       = __ldcg(hin + tid);
        hs[tid + 256] = __ldcg(hin + tid + 256);
        __syncthreads();

        float acc = 0.f;
        #pragma unroll 8
        for (int kb = 0; kb < 64; kb++) {
            uint4 w = *reinterpret_cast<const uint4*>(wbase + (size_t)kb * (G4 * 8));
            float4 h0 = *reinterpret_cast<const float4*>(&hs[kb * 8]);
            float4 h1 = *reinterpret_cast<const float4*>(&hs[kb * 8 + 4]);
            fma8(acc, w, h0, h1);
        }
        sg[tid] = acc;
        __syncthreads();

        const int t_orig = d ? (Tv - 1 - t) : t;
        if (tid < 64) {
            const float* xp = xbase + (size_t)t_orig * G4 + chunk * 64 + tid;
            float gi = sg[tid]       + xp[0];
            float gf = sg[tid + 64]  + xp[512];
            float gg = sg[tid + 128] + xp[1024];
            float go = sg[tid + 192] + xp[1536];
            float cy, hy;
            if (t_orig < s_len) {
                float si = 1.f / (1.f + expf(-gi));
                float sf = 1.f / (1.f + expf(-gf));
                float so = 1.f / (1.f + expf(-go));
                float tg = tanhf(gg);
                cy = sf * sc[tid] + si * tg;
                hy = so * tanhf(cy);
            } else {
                cy = 0.f; hy = 0.f;
            }
            sc[tid] = cy;
            hout[cell] = hy;
            out[((size_t)(b * Tv + t_orig)) * (2 * Cv) + d * Cv + cell] = hy;
        }
        __threadfence();
        __syncthreads();
        // software grid barrier (monotonic counter; continues across the two launches)
        if (tid == 0) {
            atomicAdd(&g_bar_cnt, 1);
            const int target = (d * Tv + t + 1) * 256;
            while (*((volatile int*)&g_bar_cnt) < target) { }
        }
        __syncthreads();
        __threadfence();
    }
}

// ---------------- launch ----------------
extern "C" void kernel_launch(void* const* d_in, const int* in_sizes, int n_in,
                              void* d_out, int out_size)
{
    const float* x    = (const float*)d_in[0];
    const unsigned char* mask8 = (const unsigned char*)d_in[1];
    const int* ma     = (const int*)d_in[2];
    const int* mc     = (const int*)d_in[3];
    const float* ea   = (const float*)d_in[4];
    const float* ec   = (const float*)d_in[5];
    const float* pw1  = (const float*)d_in[6];
    const float* pb1  = (const float*)d_in[7];
    const float* pw2  = (const float*)d_in[8];
    const float* Wih  = (const float*)d_in[9];
    const float* Whh  = (const float*)d_in[10];
    const float* bb   = (const float*)d_in[11];
    const float* Wihr = (const float*)d_in[12];
    const float* Whhr = (const float*)d_in[13];
    const float* bbr  = (const float*)d_in[14];
    float* out = (float*)d_out;

    prep_kernel<<<Bv, 128>>>(mask8, ma, mc, ea, ec, pw1, pb1, pw2);
    bias_kernel<<<(2 * Bv * G4) / 256, 256>>>(bb, bbr);
    mix_hh_kernel<<<(1 << 20) / 256, 256>>>(Whh, Whhr);
    init_kernel<<<(2 * Bv * Cv + 255) / 256, 256>>>();

    mix_ih_kernel<<<(4 * G4 * 64) / 256, 256>>>(Wih);
    proj_kernel<<<dim3(16, 2, Bv), 256>>>(x, 0);
    mix_ih_kernel<<<(4 * G4 * 64) / 256, 256>>>(Wihr);
    proj_kernel<<<dim3(16, 2, Bv), 256>>>(x, 1);

    // Persistent per-direction recurrence: 67 MB fp16 weight set stays L2-resident.
    step_persist<<<256, 256>>>(0, out);
    step_persist<<<256, 256>>>(1, out);
}

// round 12
// speedup vs baseline: 3.4378x; 1.4953x over previous
#include <cuda_runtime.h>
#include <cuda_fp16.h>
#include <cstdint>
#include <cstddef>

#define Bv   32
#define Tv   256
#define Iv   512
#define Cv   512
#define G4   2048
#define NBv  8

// ---------------- scratch (static device globals; no allocations) ----------------
__device__ float g_c[Bv * NBv];              // mixture coefficients [b][n]
__device__ int   g_len[Bv];                  // sequence lengths
__device__ float g_bias[2 * Bv * G4];        // mixed biases per dir
__device__ __align__(16) float  g_Wih_mix[(size_t)Bv * G4 * Iv];     // 134 MB fp32 (reused per dir)
__device__ __align__(16) float  g_Xproj[(size_t)2 * Bv * Tv * G4];   // 268 MB fp32 [d][b][t][2048]
__device__ __align__(16) __half g_h16[2 * Bv * Cv];                  // h state f16 [d][b][cell]
__device__ int g_bar_cnt;                                            // grid barrier counter

// ---------------- prep: lengths + mixture coefficients ----------------
// mask dtype detection: batch 0 has length T (all-true row), so the first 4
// bytes are: uint8 -> 0x01010101, int32 -> 0x00000001, float32 -> 0x3f800000.
__global__ __launch_bounds__(128) void prep_kernel(
    const unsigned char* __restrict__ mask8,
    const int* __restrict__ ma, const int* __restrict__ mc,
    const float* __restrict__ ea, const float* __restrict__ ec,
    const float* __restrict__ pw1, const float* __restrict__ pb1,
    const float* __restrict__ pw2)
{
    int b = blockIdx.x, tid = threadIdx.x;
    __shared__ float q[128];
    __shared__ float h1[64];
    __shared__ float lg[8];
    __shared__ int   redi[128];
    __shared__ int   mode;

    if (tid == 0) {
        unsigned w0 = *reinterpret_cast<const unsigned*>(mask8);
        if (w0 == 0x01010101u)      mode = 0;   // uint8
        else if (w0 == 1u)          mode = 1;   // int32
        else                        mode = 2;   // float32
    }
    __syncthreads();

    int cnt = 0;
    if (mode == 0) {
        cnt = (int)mask8[b * Tv + tid] + (int)mask8[b * Tv + 128 + tid];
    } else if (mode == 1) {
        const int* m32 = reinterpret_cast<const int*>(mask8);
        cnt = m32[b * Tv + tid] + m32[b * Tv + 128 + tid];
    } else {
        const float* mf = reinterpret_cast<const float*>(mask8);
        cnt = (mf[b * Tv + tid] != 0.f) + (mf[b * Tv + 128 + tid] != 0.f);
    }
    redi[tid] = cnt;
    __syncthreads();
    for (int s = 64; s > 0; s >>= 1) {
        if (tid < s) redi[tid] += redi[tid + s];
        __syncthreads();
    }
    if (tid == 0) g_len[b] = redi[0];

    int a = ma[b], cidx = mc[b];
    if (tid < 64) q[tid] = ea[a * 64 + tid];
    else          q[tid] = ec[cidx * 64 + (tid - 64)];
    __syncthreads();

    if (tid < 64) {
        float s = pb1[tid];
        #pragma unroll 8
        for (int i = 0; i < 128; i++) s += q[i] * pw1[i * 64 + tid];
        h1[tid] = tanhf(s);
    }
    __syncthreads();
    if (tid < 8) {
        float s = 0.f;
        #pragma unroll 8
        for (int i = 0; i < 64; i++) s += h1[i] * pw2[i * 8 + tid];
        lg[tid] = s;
    }
    __syncthreads();
    if (tid == 0) {
        float m = lg[0];
        #pragma unroll
        for (int n = 1; n < 8; n++) m = fmaxf(m, lg[n]);
        float e[8], sum = 0.f;
        #pragma unroll
        for (int n = 0; n < 8; n++) { e[n] = expf(lg[n] - m); sum += e[n]; }
        float inv = 1.f / sum;
        #pragma unroll
        for (int n = 0; n < 8; n++) g_c[b * 8 + n] = e[n] * inv;
    }
}

// ---------------- mixed biases ----------------
__global__ __launch_bounds__(256) void bias_kernel(
    const float* __restrict__ bf, const float* __restrict__ br)
{
    int idx = blockIdx.x * 256 + threadIdx.x;      // 2*32*2048 = 131072
    int g = idx & 2047;
    int b = (idx >> 11) & 31;
    int d = idx >> 16;
    const float* src = d ? br : bf;                // [8][2048]
    float s = 0.f;
    #pragma unroll
    for (int n = 0; n < 8; n++) s += g_c[b * 8 + n] * src[n * G4 + g];
    g_bias[idx] = s;
}

// ---------------- mix W_ih -> fp32 (one direction at a time) ----------------
__global__ __launch_bounds__(256) void mix_ih_kernel(const float* __restrict__ Wsrc)
{
    __shared__ float cs[Bv * NBv];
    if (threadIdx.x < Bv * NBv) cs[threadIdx.x] = g_c[threadIdx.x];
    __syncthreads();

    int item = blockIdx.x * 256 + threadIdx.x;   // 4*2048*64 = 524288
    int i8 = item & 63;
    int g  = (item >> 6) & 2047;
    int bg = item >> 17;                          // 0..3

    float acc[8][8];
    #pragma unroll
    for (int i = 0; i < 8; i++)
        #pragma unroll
        for (int j = 0; j < 8; j++) acc[i][j] = 0.f;

    const float* wp0 = Wsrc + (size_t)g * 512 + i8 * 8;
    #pragma unroll
    for (int n = 0; n < 8; n++) {
        const float* wp = wp0 + (size_t)n * (G4 * 512);
        float4 wa = *reinterpret_cast<const float4*>(wp);
        float4 wb = *reinterpret_cast<const float4*>(wp + 4);
        #pragma unroll
        for (int bb = 0; bb < 8; bb++) {
            float cc = cs[(bg * 8 + bb) * 8 + n];
            acc[bb][0] += cc * wa.x; acc[bb][1] += cc * wa.y;
            acc[bb][2] += cc * wa.z; acc[bb][3] += cc * wa.w;
            acc[bb][4] += cc * wb.x; acc[bb][5] += cc * wb.y;
            acc[bb][6] += cc * wb.z; acc[bb][7] += cc * wb.w;
        }
    }
    #pragma unroll
    for (int bb = 0; bb < 8; bb++) {
        int b = bg * 8 + bb;
        float* dst = g_Wih_mix + ((size_t)(b * G4 + g)) * 512 + i8 * 8;
        *reinterpret_cast<float4*>(dst)     = make_float4(acc[bb][0], acc[bb][1], acc[bb][2], acc[bb][3]);
        *reinterpret_cast<float4*>(dst + 4) = make_float4(acc[bb][4], acc[bb][5], acc[bb][6], acc[bb][7]);
    }
}

// ---------------- input projection: Xproj[b,t,:] = Wmix[b] @ x[b,t] + bias ----------------
__global__ __launch_bounds__(256, 2) void proj_kernel(const float* __restrict__ X, int d)
{
    int b  = blockIdx.z;
    int by = blockIdx.y;
    int bx = blockIdx.x;
    const float* A  = X + (size_t)b * Tv * Iv;                 // [256][512]
    const float* Bw = g_Wih_mix + (size_t)b * G4 * Iv;         // [2048][512]
    float* C = g_Xproj + (size_t)(d * Bv + b) * Tv * G4;
    const float* bias = g_bias + (d * Bv + b) * G4;

    __shared__ __align__(16) float As[8][128];
    __shared__ __align__(16) float Bs[8][128];

    int tid = threadIdx.x;
    int lr = tid >> 1;
    int lk = (tid & 1) * 4;
    const float* aptr = A  + (size_t)(by * 128 + lr) * Iv + lk;
    const float* bptr = Bw + (size_t)(bx * 128 + lr) * Iv + lk;
    int tx = tid & 15, ty = tid >> 4;

    float acc[8][8];
    #pragma unroll
    for (int i = 0; i < 8; i++)
        #pragma unroll
        for (int j = 0; j < 8; j++) acc[i][j] = 0.f;

    float4 av = *reinterpret_cast<const float4*>(aptr);
    float4 bv = *reinterpret_cast<const float4*>(bptr);

    for (int k0 = 0; k0 < Iv; k0 += 8) {
        __syncthreads();
        As[lk + 0][lr] = av.x; As[lk + 1][lr] = av.y; As[lk + 2][lr] = av.z; As[lk + 3][lr] = av.w;
        Bs[lk + 0][lr] = bv.x; Bs[lk + 1][lr] = bv.y; Bs[lk + 2][lr] = bv.z; Bs[lk + 3][lr] = bv.w;
        __syncthreads();
        if (k0 + 8 < Iv) {
            av = *reinterpret_cast<const float4*>(aptr + k0 + 8);
            bv = *reinterpret_cast<const float4*>(bptr + k0 + 8);
        }
        #pragma unroll
        for (int kk = 0; kk < 8; kk++) {
            float4 aA = *reinterpret_cast<const float4*>(&As[kk][ty * 8]);
            float4 aB = *reinterpret_cast<const float4*>(&As[kk][ty * 8 + 4]);
            float4 bA = *reinterpret_cast<const float4*>(&Bs[kk][tx * 8]);
            float4 bB = *reinterpret_cast<const float4*>(&Bs[kk][tx * 8 + 4]);
            float ar[8] = {aA.x, aA.y, aA.z, aA.w, aB.x, aB.y, aB.z, aB.w};
            float br[8] = {bA.x, bA.y, bA.z, bA.w, bB.x, bB.y, bB.z, bB.w};
            #pragma unroll
            for (int i = 0; i < 8; i++)
                #pragma unroll
                for (int j = 0; j < 8; j++)
                    acc[i][j] += ar[i] * br[j];
        }
    }

    #pragma unroll
    for (int i = 0; i < 8; i++) {
        int row = by * 128 + ty * 8 + i;
        #pragma unroll
        for (int j = 0; j < 8; j += 4) {
            int col = bx * 128 + tx * 8 + j;
            float4 v = make_float4(acc[i][j + 0] + bias[col + 0],
                                   acc[i][j + 1] + bias[col + 1],
                                   acc[i][j + 2] + bias[col + 2],
                                   acc[i][j + 3] + bias[col + 3]);
            *reinterpret_cast<float4*>(&C[(size_t)row * G4 + col]) = v;
        }
    }
}

// ---------------- zero recurrent state + barrier ----------------
__global__ void init_kernel()
{
    int i = blockIdx.x * 256 + threadIdx.x;
    if (i < (2 * Bv * Cv) / 2) reinterpret_cast<unsigned*>(g_h16)[i] = 0u;  // 16384 u32
    if (i == 0) g_bar_cnt = 0;
}

// ---------------- persistent tensor recurrence, one direction ----------------
// grid = 128 blocks x 256 threads (8 warps). Block bid owns cells bid*4..bid*4+3
// (all 4 gates -> 16 gate-rows), warp w = basis n. A fragments (f16 basis
// weights) live in registers for the entire 256-step loop: zero weight traffic.
// gates[row,b] = sum_n c[b,n] * (W_n[row,:] . h[b,:])  (fp32 accumulate).
#define MMA16816(D0,D1,D2,D3,A0,A1,A2,A3,B0,B1) \
    asm volatile("mma.sync.aligned.m16n8k16.row.col.f32.f16.f16.f32 " \
        "{%0,%1,%2,%3}, {%4,%5,%6,%7}, {%8,%9}, {%0,%1,%2,%3};" \
        : "+f"(D0), "+f"(D1), "+f"(D2), "+f"(D3) \
        : "r"(A0), "r"(A1), "r"(A2), "r"(A3), "r"(B0), "r"(B1))

__global__ __launch_bounds__(256, 1) void rec_persist(
    const float* __restrict__ Whh, int d, float* __restrict__ out)
{
    const int bid = blockIdx.x;          // 0..127 -> cells bid*4..+3
    const int tid = threadIdx.x;
    const int wid = tid >> 5;            // warp = basis n
    const int lane = tid & 31;
    const int gid = lane >> 2;           // 0..7
    const int tig = lane & 3;            // 0..3

    // smem: hsm (32 x 260 u32, padded f16 h) overlaid with red (8*16*33 f32)
    __shared__ __align__(16) unsigned smem_buf[32 * 260];      // 33.3 KB
    float* red = reinterpret_cast<float*>(smem_buf);
    __shared__ __align__(16) float xbuf[4][32][4];             // [gate][b][j]
    __shared__ float csm[256];                                  // c[b*8+n]
    __shared__ float scs[128];                                  // c-state [j*32+b]
    __shared__ int   lensm[32];

    if (tid < 256) csm[tid] = g_c[tid];
    if (tid < 32)  lensm[tid] = g_len[tid];
    if (tid < 128) scs[tid] = 0.f;

    // ---- load A fragments: basis wid, 16 permuted rows (g*4+j), K=512 ----
    // local row r -> global gate-row: (r>>2)*512 + bid*4 + (r&3)
    uint32_t af[32][4];
    {
        const float* W = Whh + (size_t)wid * G4 * Iv;
        int r0 = gid, r1 = gid + 8;
        const float* p0 = W + (size_t)((r0 >> 2) * 512 + bid * 4 + (r0 & 3)) * Iv;
        const float* p1 = W + (size_t)((r1 >> 2) * 512 + bid * 4 + (r1 & 3)) * Iv;
        #pragma unroll
        for (int kt = 0; kt < 32; kt++) {
            int c0 = kt * 16 + tig * 2;
            float2 x0 = *reinterpret_cast<const float2*>(p0 + c0);
            float2 x1 = *reinterpret_cast<const float2*>(p1 + c0);
            float2 x2 = *reinterpret_cast<const float2*>(p0 + c0 + 8);
            float2 x3 = *reinterpret_cast<const float2*>(p1 + c0 + 8);
            __half2 h0 = __floats2half2_rn(x0.x, x0.y);
            __half2 h1 = __floats2half2_rn(x1.x, x1.y);
            __half2 h2 = __floats2half2_rn(x2.x, x2.y);
            __half2 h3 = __floats2half2_rn(x3.x, x3.y);
            af[kt][0] = *reinterpret_cast<uint32_t*>(&h0);
            af[kt][1] = *reinterpret_cast<uint32_t*>(&h1);
            af[kt][2] = *reinterpret_cast<uint32_t*>(&h2);
            af[kt][3] = *reinterpret_cast<uint32_t*>(&h3);
        }
    }

    const uint4* hsrc = reinterpret_cast<const uint4*>(g_h16 + d * (Bv * Cv));
    __half* hdst = g_h16 + d * (Bv * Cv);
    const float* xpro = g_Xproj + (size_t)d * Bv * Tv * G4;
    const float csa = (tid < 128) ? 0.f : 0.f; (void)csa;

    // prefetch address prep for Xproj (thread tid<128: gate=tid>>5, b=tid&31)
    const int pf_gate = tid >> 5;        // 0..3 (valid when tid<128)
    const int pf_b = tid & 31;
    unsigned xb_s = (unsigned)__cvta_generic_to_shared(&xbuf[pf_gate & 3][pf_b][0]);

    for (int t = 0; t < Tv; t++) {
        const int t_orig = d ? (Tv - 1 - t) : t;

        // -- prefetch Xproj for this step (cp.async, 16B per thread, tid<128) --
        if (tid < 128) {
            const float* gp = xpro + ((size_t)(pf_b * Tv + t_orig)) * G4
                            + pf_gate * 512 + bid * 4;
            asm volatile("cp.async.ca.shared.global [%0], [%1], 16;"
                         :: "r"(xb_s), "l"(gp));
            asm volatile("cp.async.commit_group;");
        }

        // -- load h (f16, 32 KB) L2-coherent into padded smem --
        #pragma unroll
        for (int i = 0; i < 8; i++) {
            int idx4 = i * 1024 + tid * 4;          // u32 units
            int row = idx4 >> 8, col = idx4 & 255;
            uint4 v = __ldcg(hsrc + (i * 256 + tid));
            *reinterpret_cast<uint4*>(&smem_buf[row * 260 + col]) = v;
        }
        __syncthreads();

        // -- MMA: D_n[16 x 32] = A_n @ h^T --
        float D[4][4];
        #pragma unroll
        for (int i = 0; i < 4; i++)
            #pragma unroll
            for (int j = 0; j < 4; j++) D[i][j] = 0.f;

        #pragma unroll
        for (int kt = 0; kt < 32; kt++) {
            #pragma unroll
            for (int nt = 0; nt < 4; nt++) {
                uint32_t b0 = smem_buf[(nt * 8 + gid) * 260 + kt * 8 + tig];
                uint32_t b1 = smem_buf[(nt * 8 + gid) * 260 + kt * 8 + tig + 4];
                MMA16816(D[nt][0], D[nt][1], D[nt][2], D[nt][3],
                         af[kt][0], af[kt][1], af[kt][2], af[kt][3], b0, b1);
            }
        }
        __syncthreads();   // all warps done reading hsm before red overlay

        // -- scale by c[b,n], store partials to red[n][row][b] (33-pad) --
        #pragma unroll
        for (int nt = 0; nt < 4; nt++) {
            int c0 = nt * 8 + tig * 2;
            float s0 = csm[c0 * 8 + wid];
            float s1 = csm[(c0 + 1) * 8 + wid];
            red[(wid * 16 + gid) * 33 + c0]         = D[nt][0] * s0;
            red[(wid * 16 + gid) * 33 + c0 + 1]     = D[nt][1] * s1;
            red[(wid * 16 + gid + 8) * 33 + c0]     = D[nt][2] * s0;
            red[(wid * 16 + gid + 8) * 33 + c0 + 1] = D[nt][3] * s1;
        }
        __syncthreads();

        // -- reduce bases + pointwise LSTM (tid<128: j=tid>>5, b=tid&31) --
        if (tid < 128) {
            const int j = tid >> 5;
            const int b = tid & 31;
            float gi = 0.f, gf = 0.f, gg = 0.f, go = 0.f;
            #pragma unroll
            for (int n = 0; n < 8; n++) {
                gi += red[(n * 16 + j) * 33 + b];
                gf += red[(n * 16 + 4 + j) * 33 + b];
                gg += red[(n * 16 + 8 + j) * 33 + b];
                go += red[(n * 16 + 12 + j) * 33 + b];
            }
            asm volatile("cp.async.wait_group 0;" ::: "memory");
            gi += xbuf[0][b][j];
            gf += xbuf[1][b][j];
            gg += xbuf[2][b][j];
            go += xbuf[3][b][j];

            const int cell = bid * 4 + j;
            float cprev = scs[tid];
            float cy, hy;
            if (t_orig < lensm[b]) {
                float si = 1.f / (1.f + expf(-gi));
                float sf = 1.f / (1.f + expf(-gf));
                float so = 1.f / (1.f + expf(-go));
                float tg = tanhf(gg);
                cy = sf * cprev + si * tg;
                hy = so * tanhf(cy);
            } else {
                cy = 0.f; hy = 0.f;
            }
            scs[tid] = cy;
            // h f16 (L2-coherent store)
            __half hv = __float2half(hy);
            unsigned short hu = *reinterpret_cast<unsigned short*>(&hv);
            asm volatile("st.global.cg.u16 [%0], %1;"
                         :: "l"(hdst + b * Cv + cell), "h"(hu));
            out[((size_t)(b * Tv + t_orig)) * (2 * Cv) + d * Cv + cell] = hy;
        }
        __threadfence();
        __syncthreads();
        // -- software grid barrier (monotonic across both direction launches) --
        if (tid == 0) {
            atomicAdd(&g_bar_cnt, 1);
            const int target = (d * Tv + t + 1) * 128;
            while (*((volatile int*)&g_bar_cnt) < target) { }
        }
        __syncthreads();
        __threadfence();
    }
}

// ---------------- launch ----------------
extern "C" void kernel_launch(void* const* d_in, const int* in_sizes, int n_in,
                              void* d_out, int out_size)
{
    const float* x    = (const float*)d_in[0];
    const unsigned char* mask8 = (const unsigned char*)d_in[1];
    const int* ma     = (const int*)d_in[2];
    const int* mc     = (const int*)d_in[3];
    const float* ea   = (const float*)d_in[4];
    const float* ec   = (const float*)d_in[5];
    const float* pw1  = (const float*)d_in[6];
    const float* pb1  = (const float*)d_in[7];
    const float* pw2  = (const float*)d_in[8];
    const float* Wih  = (const float*)d_in[9];
    const float* Whh  = (const float*)d_in[10];
    const float* bb   = (const float*)d_in[11];
    const float* Wihr = (const float*)d_in[12];
    const float* Whhr = (const float*)d_in[13];
    const float* bbr  = (const float*)d_in[14];
    float* out = (float*)d_out;

    prep_kernel<<<Bv, 128>>>(mask8, ma, mc, ea, ec, pw1, pb1, pw2);
    bias_kernel<<<(2 * Bv * G4) / 256, 256>>>(bb, bbr);
    init_kernel<<<(16384 + 255) / 256, 256>>>();

    mix_ih_kernel<<<(4 * G4 * 64) / 256, 256>>>(Wih);
    proj_kernel<<<dim3(16, 2, Bv), 256>>>(x, 0);
    mix_ih_kernel<<<(4 * G4 * 64) / 256, 256>>>(Wihr);
    proj_kernel<<<dim3(16, 2, Bv), 256>>>(x, 1);

    // Persistent tensor-core recurrence: basis weights register-resident,
    // ~zero weight traffic per step.
    rec_persist<<<128, 256>>>(Whh, 0, out);
    rec_persist<<<128, 256>>>(Whhr, 1, out);
}